// round 14
// baseline (speedup 1.0000x reference)
#include <cuda_runtime.h>
#include <cuda_fp16.h>
#include <cstdint>

#define DIMD  1024
#define BATCH 8
#define SEQ   2048

// ---------------------------------------------------------------------------
// Scratch (static device memory — no allocations)
// ---------------------------------------------------------------------------
__device__ __half g_xh  [(size_t)BATCH * SEQ * DIMD];      // x fp16
__device__ __half g_Wc  [(size_t)2 * DIMD * DIMD];         // [W1;W2] fp16
__device__ float  g_bc  [2 * DIMD];                        // [b1;b2] fp32
__device__ __half g_VKh [(size_t)BATCH * SEQ * 2 * DIMD];  // cols 0-1023 V(==Q), 1024-2047 K
__device__ __half g_Sh  [(size_t)BATCH * SEQ * SEQ];       // exp(scores) fp16
__device__ float  g_ps  [(size_t)BATCH * SEQ * 32];        // partial row sums

// ---------------------------------------------------------------------------
// Helpers
// ---------------------------------------------------------------------------
__device__ __forceinline__ uint32_t smem_u32(const void* p) {
    return (uint32_t)__cvta_generic_to_shared(p);
}
// SW128 swizzle for 128-byte rows: bits[6:4] ^= bits[9:7]
__device__ __forceinline__ uint32_t swz(uint32_t o) { return o ^ ((o >> 3) & 0x70); }
// swizzle for 256-byte rows: bits[6:4] ^= bits[10:8]
__device__ __forceinline__ uint32_t swzB(uint32_t o) { return o ^ ((o >> 4) & 0x70); }

__device__ __forceinline__ void cp_async16(uint32_t dst, const void* src) {
    asm volatile("cp.async.cg.shared.global [%0], [%1], 16;" :: "r"(dst), "l"(src));
}
__device__ __forceinline__ void cp_commit() {
    asm volatile("cp.async.commit_group;" ::: "memory");
}
__device__ __forceinline__ void cp_wait1() {
    asm volatile("cp.async.wait_group 1;" ::: "memory");
}
__device__ __forceinline__ void ldsm_x4(uint32_t* r, uint32_t addr) {
    asm volatile("ldmatrix.sync.aligned.m8n8.x4.shared.b16 {%0,%1,%2,%3}, [%4];"
                 : "=r"(r[0]), "=r"(r[1]), "=r"(r[2]), "=r"(r[3]) : "r"(addr));
}
__device__ __forceinline__ void ldsm_x4_t(uint32_t* r, uint32_t addr) {
    asm volatile("ldmatrix.sync.aligned.m8n8.x4.trans.shared.b16 {%0,%1,%2,%3}, [%4];"
                 : "=r"(r[0]), "=r"(r[1]), "=r"(r[2]), "=r"(r[3]) : "r"(addr));
}
__device__ __forceinline__ void mma16816(float* c, const uint32_t* a,
                                         uint32_t b0, uint32_t b1) {
    asm volatile("mma.sync.aligned.m16n8k16.row.col.f32.f16.f16.f32 "
                 "{%0,%1,%2,%3}, {%4,%5,%6,%7}, {%8,%9}, {%0,%1,%2,%3};"
                 : "+f"(c[0]), "+f"(c[1]), "+f"(c[2]), "+f"(c[3])
                 : "r"(a[0]), "r"(a[1]), "r"(a[2]), "r"(a[3]), "r"(b0), "r"(b1));
}
// exp(x) for two halfs at once: ex2.approx.f16x2 (inputs pre-scaled by log2e)
__device__ __forceinline__ __half2 h2_ex2(__half2 x) {
    __half2 r;
    asm("ex2.approx.f16x2 %0, %1;" : "=r"(*(uint32_t*)&r) : "r"(*(const uint32_t*)&x));
    return r;
}

// ---------------------------------------------------------------------------
// fp16 tensor-core GEMM, 2 N-tiles per CTA through one continuous ring.
//   TRB=0 (NT): C = alpha * A[M,K] @ B[N,K]^T
//   TRB=1 (NN): C = alpha * A[M,K] @ B[K,N]   (ldsm.trans)
// Block tile 128x128 x2 adjacent N-tiles, BK=64, 3-stage cp.async ring spanning
// both tiles, 128 threads (4 warps 2x2), warp tile 64x64, 2 CTAs/SM.
// tshift = log2(K/64).
// mode 0: half out + fp32 bias(col).   mode 1: float out.   mode 2: half out.
// mode 3: half out = exp(alpha*acc) via f16x2 ex2, psums -> g_ps.
// mode 4: float out * rowinv; inv computed in-prologue from g_ps into smem.
// ---------------------------------------------------------------------------
#define BM 128
#define BN 128
#define BKH 64
#define STG 32768
#define NSTAGE 3
#define SMEM_SZ (NSTAGE * STG + 512)

template<int TRB>
__global__ __launch_bounds__(128, 2)
void mm_h16(const __half* __restrict__ A, const __half* __restrict__ B,
            const float* __restrict__ aux, void* __restrict__ Cout,
            int lda, int ldb, int ldc,
            size_t zA, size_t zB, size_t zC,
            int tshift, float alpha, int mode)
{
    extern __shared__ char smem[];
    const uint32_t sbase = smem_u32(smem);
    float* sinv = (float*)(smem + NSTAGE * STG);   // 128 floats (mode 4)
    const int tid = threadIdx.x;
    const int wid = tid >> 5;
    const int lane = tid & 31;

    const int bz = blockIdx.z;
    A += (size_t)bz * zA;
    B += (size_t)bz * zB;

    const int tile_m = blockIdx.y * BM;
    const int tile_n0 = blockIdx.x * (2 * BN);     // first of two N-tiles
    const int tmask = (1 << tshift) - 1;
    const int G = 2 << tshift;                     // total iterations (2 tiles)

    // --- A loader: 8 x 16B chunks per thread (same for both tiles) ---
    const int rA = tid >> 3;
    const int kcA = tid & 7;
    const __half* gA = A + (size_t)(tile_m + rA) * lda + kcA * 8;
    const uint32_t dA = swz((uint32_t)(rA * 128 + kcA * 16));

    // --- B loader: base for tile 0; bumpB = element offset to tile 1 ---
    const __half* gB;
    uint32_t dB;
    uint32_t bumpB;
    if (TRB == 0) {
        gB = B + (size_t)(tile_n0 + rA) * ldb + kcA * 8;
        dB = 16384u + swz((uint32_t)(rA * 128 + kcA * 16));
        bumpB = (uint32_t)(BN * ldb);              // +128 rows
    } else {
        const int rB = tid >> 4;
        const int cB = tid & 15;
        gB = B + (size_t)rB * ldb + tile_n0 + cB * 8;
        dB = 16384u + swzB((uint32_t)(rB * 256 + cB * 16));
        bumpB = (uint32_t)BN;                      // +128 columns
    }

#define LOAD_A(s, tq) do { \
        uint32_t sb_ = sbase + (uint32_t)(s) * STG; \
        const __half* pa_ = gA + (size_t)(tq) * BKH; \
        _Pragma("unroll") \
        for (int i_ = 0; i_ < 8; i_++) \
            cp_async16(sb_ + dA + i_ * 2048u, pa_ + (size_t)(16 * i_) * lda); \
    } while (0)
#define LOAD_B(s, tq, boff) do { \
        uint32_t sb_ = sbase + (uint32_t)(s) * STG; \
        if (TRB == 0) { \
            const __half* pb_ = gB + (boff) + (size_t)(tq) * BKH; \
            _Pragma("unroll") \
            for (int i_ = 0; i_ < 8; i_++) \
                cp_async16(sb_ + dB + i_ * 2048u, pb_ + (size_t)(16 * i_) * ldb); \
        } else { \
            const __half* pb_ = gB + (boff) + (size_t)(tq) * BKH * ldb; \
            _Pragma("unroll") \
            for (int i_ = 0; i_ < 8; i_++) \
                cp_async16(sb_ + dB + i_ * 2048u, pb_ + (size_t)(8 * i_) * ldb); \
        } \
    } while (0)

    // Prologue: stages 0,1 (tile 0; T >= 16 so both within tile 0)
    #pragma unroll
    for (int p = 0; p < 2; p++) {
        LOAD_A(p, p);
        LOAD_B(p, p, 0u);
        cp_commit();
    }

    // mode 4: 1/rowsum for this CTA's 128 rows while cp.async streams.
    if (mode == 4) {
        const float* p = g_ps + ((size_t)(bz * SEQ + tile_m + tid)) * 32;
        float s = 0.f;
        #pragma unroll
        for (int i = 0; i < 8; i++) {
            float4 v = ((const float4*)p)[i];
            s += (v.x + v.y) + (v.z + v.w);
        }
        sinv[tid] = 1.0f / s;
    }

    // --- compute plan ---
    const int wm = wid & 1;
    const int wn = wid >> 1;
    const int lr = lane & 15;
    const int lcb = (lane >> 4) * 16;

    uint32_t aoff0[4], boff0[4];
    #pragma unroll
    for (int mi = 0; mi < 4; mi++)
        aoff0[mi] = swz((uint32_t)((wm * 64 + mi * 16 + lr) * 128 + lcb));
    if (TRB == 0) {
        #pragma unroll
        for (int nb = 0; nb < 4; nb++)
            boff0[nb] = 16384u + swz((uint32_t)((wn * 64 + nb * 16 + lr) * 128 + lcb));
    } else {
        #pragma unroll
        for (int nb = 0; nb < 4; nb++)
            boff0[nb] = 16384u + swzB((uint32_t)(lr * 256 + wn * 128 + nb * 32 + lcb));
    }

#define LDFRAG(af, bf, sa_, ks_) do { \
        _Pragma("unroll") \
        for (int mi_ = 0; mi_ < 4; mi_++) \
            ldsm_x4((af)[mi_], (sa_) + (aoff0[mi_] ^ (uint32_t)((ks_) * 32))); \
        if (TRB == 0) { \
            _Pragma("unroll") \
            for (int nb_ = 0; nb_ < 4; nb_++) \
                ldsm_x4((bf)[nb_], (sa_) + (boff0[nb_] ^ (uint32_t)((ks_) * 32))); \
        } else { \
            _Pragma("unroll") \
            for (int nb_ = 0; nb_ < 4; nb_++) \
                ldsm_x4_t((bf)[nb_], (sa_) + boff0[nb_] + (uint32_t)((ks_) * 4096)); \
        } \
    } while (0)

#define MMABLK(af, bf) do { \
        _Pragma("unroll") \
        for (int mi_ = 0; mi_ < 4; mi_++) \
            _Pragma("unroll") \
            for (int ni_ = 0; ni_ < 8; ni_++) { \
                uint32_t b0_ = (TRB == 0) ? (bf)[ni_ >> 1][ni_ & 1] \
                                          : (bf)[ni_ >> 1][(ni_ & 1) * 2]; \
                uint32_t b1_ = (TRB == 0) ? (bf)[ni_ >> 1][(ni_ & 1) + 2] \
                                          : (bf)[ni_ >> 1][(ni_ & 1) * 2 + 1]; \
                mma16816(acc[mi_][ni_], (af)[mi_], b0_, b1_); \
            } \
    } while (0)

    float acc[4][8][4] = {};
    uint32_t a0[4][4], b0[4][4], a1[4][4], b1[4][4];

    const int er = lane >> 2;
    const int ec = (lane & 3) * 2;
    const float l2e_alpha = alpha * 1.4426950408889634f;

    cp_wait1();
    __syncthreads();
    LDFRAG(a0, b0, sbase, 0);

    for (int g = 0; g < G; g++) {
        const uint32_t sa = sbase + (uint32_t)(g % NSTAGE) * STG;
        const bool pf = (g + 2 < G);
        const int ps = (g + 2) % NSTAGE;
        const int q = g + 2;
        const int tq = q & tmask;
        const uint32_t bo = (q >> tshift) ? bumpB : 0u;

        LDFRAG(a1, b1, sa, 1);
        MMABLK(a0, b0);                // ks 0
        if (pf) LOAD_A(ps, tq);        // global loads issued mid-compute
        LDFRAG(a0, b0, sa, 2);
        MMABLK(a1, b1);                // ks 1
        if (pf) LOAD_B(ps, tq, bo);
        LDFRAG(a1, b1, sa, 3);
        MMABLK(a0, b0);                // ks 2

        cp_commit();
        cp_wait1();
        __syncthreads();

        if (g + 1 < G)
            LDFRAG(a0, b0, sbase + (uint32_t)((g + 1) % NSTAGE) * STG, 0);
        MMABLK(a1, b1);                // ks 3

        // --- per-tile epilogue at tile boundary (ring keeps streaming) ---
        if ((g & tmask) == tmask) {
            const int jt = g >> tshift;           // 0 or 1
            const int tile_n = tile_n0 + jt * BN;

            if (mode == 1 || mode == 4) {
                float* C = (float*)Cout + (size_t)bz * zC;
                #pragma unroll
                for (int mi = 0; mi < 4; mi++) {
                    int mrow = wm * 64 + mi * 16 + er;
                    int m0 = tile_m + mrow;
                    float s0 = alpha, s1 = alpha;
                    if (mode == 4) { s0 = sinv[mrow]; s1 = sinv[mrow + 8]; }
                    #pragma unroll
                    for (int ni = 0; ni < 8; ni++) {
                        int n0 = tile_n + wn * 64 + ni * 8 + ec;
                        float* c = acc[mi][ni];
                        *(float2*)(C + (size_t)m0 * ldc + n0) =
                            make_float2(c[0] * s0, c[1] * s0);
                        *(float2*)(C + (size_t)(m0 + 8) * ldc + n0) =
                            make_float2(c[2] * s1, c[3] * s1);
                    }
                }
            } else {
                __half* C = (__half*)Cout + (size_t)bz * zC;
                float psum[4][2];
                #pragma unroll
                for (int mi = 0; mi < 4; mi++) { psum[mi][0] = 0.f; psum[mi][1] = 0.f; }

                #pragma unroll
                for (int mi = 0; mi < 4; mi++) {
                    #pragma unroll
                    for (int ni = 0; ni < 8; ni++) {
                        int m0 = tile_m + wm * 64 + mi * 16 + er;
                        int n0 = tile_n + wn * 64 + ni * 8 + ec;
                        float* c = acc[mi][ni];
                        __half2 h01, h23;
                        if (mode == 3) {
                            h01 = h2_ex2(__floats2half2_rn(c[0] * l2e_alpha, c[1] * l2e_alpha));
                            h23 = h2_ex2(__floats2half2_rn(c[2] * l2e_alpha, c[3] * l2e_alpha));
                            float2 f01 = __half22float2(h01);
                            float2 f23 = __half22float2(h23);
                            psum[mi][0] += f01.x + f01.y;
                            psum[mi][1] += f23.x + f23.y;
                        } else {
                            float bx = 0.f, by = 0.f;
                            if (mode == 0) { bx = aux[n0]; by = aux[n0 + 1]; }
                            h01 = __floats2half2_rn(c[0] * alpha + bx, c[1] * alpha + by);
                            h23 = __floats2half2_rn(c[2] * alpha + bx, c[3] * alpha + by);
                        }
                        *(__half2*)(C + (size_t)m0 * ldc + n0) = h01;
                        *(__half2*)(C + (size_t)(m0 + 8) * ldc + n0) = h23;
                    }
                }

                if (mode == 3) {
                    const int bxg = blockIdx.x * 2 + jt;   // global N-tile index
                    #pragma unroll
                    for (int mi = 0; mi < 4; mi++) {
                        #pragma unroll
                        for (int h = 0; h < 2; h++) {
                            float v = psum[mi][h];
                            v += __shfl_xor_sync(0xffffffffu, v, 1);
                            v += __shfl_xor_sync(0xffffffffu, v, 2);
                            if ((lane & 3) == 0) {
                                int row = bz * SEQ + tile_m + wm * 64 + mi * 16 + er + h * 8;
                                g_ps[(size_t)row * 32 + bxg * 2 + wn] = v;
                            }
                        }
                    }
                }
            }

            // reset accumulators for the next tile
            #pragma unroll
            for (int mi = 0; mi < 4; mi++)
                #pragma unroll
                for (int ni = 0; ni < 8; ni++)
                    #pragma unroll
                    for (int qq = 0; qq < 4; qq++)
                        acc[mi][ni][qq] = 0.0f;
        }
    }
#undef LOAD_A
#undef LOAD_B
#undef LDFRAG
#undef MMABLK
}

// ---------------------------------------------------------------------------
// Combined prep: xh = fp16(x), Wc = fp16([W1;W2]), bc = [b1;b2]
// ---------------------------------------------------------------------------
__global__ __launch_bounds__(256)
void prep_all(const float* __restrict__ x,
              const float* __restrict__ W1, const float* __restrict__ W2,
              const float* __restrict__ b1, const float* __restrict__ b2,
              __half* __restrict__ xh, __half* __restrict__ Wc,
              float* __restrict__ bc)
{
    const long long nx4 = (long long)BATCH * SEQ * DIMD / 4;
    const long long nw4 = (long long)DIMD * DIMD / 4;
    long long i = (long long)blockIdx.x * blockDim.x + threadIdx.x;
    long long stride = (long long)gridDim.x * blockDim.x;

    for (long long j = i; j < nx4; j += stride) {
        float4 v = ((const float4*)x)[j];
        ((__half2*)xh)[2 * j + 0] = __floats2half2_rn(v.x, v.y);
        ((__half2*)xh)[2 * j + 1] = __floats2half2_rn(v.z, v.w);
    }
    for (long long j = i; j < 2 * nw4; j += stride) {
        const float* src = (j < nw4) ? W1 : W2;
        long long k = (j < nw4) ? j : j - nw4;
        float4 v = ((const float4*)src)[k];
        ((__half2*)Wc)[2 * j + 0] = __floats2half2_rn(v.x, v.y);
        ((__half2*)Wc)[2 * j + 1] = __floats2half2_rn(v.z, v.w);
    }
    for (long long j = i; j < 2 * DIMD; j += stride)
        bc[j] = (j < DIMD) ? b1[j] : b2[j - DIMD];
}

// ---------------------------------------------------------------------------
// Launch
// ---------------------------------------------------------------------------
extern "C" void kernel_launch(void* const* d_in, const int* in_sizes, int n_in,
                              void* d_out, int out_size)
{
    const float* x  = (const float*)d_in[0];
    const float* W1 = (const float*)d_in[1];
    const float* b1 = (const float*)d_in[2];
    const float* W2 = (const float*)d_in[3];
    const float* b2 = (const float*)d_in[4];
    float* out = (float*)d_out;

    __half *pxh, *pWc, *pVKh, *pSh;
    float *pbc;
    cudaGetSymbolAddress((void**)&pxh,  g_xh);
    cudaGetSymbolAddress((void**)&pWc,  g_Wc);
    cudaGetSymbolAddress((void**)&pbc,  g_bc);
    cudaGetSymbolAddress((void**)&pVKh, g_VKh);
    cudaGetSymbolAddress((void**)&pSh,  g_Sh);

    cudaFuncSetAttribute(mm_h16<0>, cudaFuncAttributeMaxDynamicSharedMemorySize, SMEM_SZ);
    cudaFuncSetAttribute(mm_h16<1>, cudaFuncAttributeMaxDynamicSharedMemorySize, SMEM_SZ);

    const float scale = 1.0f / 32.0f;  // 1/sqrt(1024)

    // 1. fp32 -> fp16 inputs/weights/biases (one kernel)
    prep_all<<<2048, 256>>>(x, W1, W2, b1, b2, pxh, pWc, pbc);

    // 2. [V | K] = fp16(x @ [W1;W2]^T + [b1;b2]) : M=16384, N=2048, K=1024 (NT)
    //    K=1024 -> T=16 (tshift=4); 2 N-tiles/CTA -> grid.x = 8
    mm_h16<0><<<dim3(DIMD / BN, BATCH * SEQ / BM, 1), 128, SMEM_SZ>>>(
        pxh, pWc, pbc, pVKh,
        DIMD, DIMD, 2 * DIMD, 0, 0, 0,
        4, 1.0f, 0);

    // 3. P = fp16(exp(scale * K . V)) + partial row sums (NT, mode 3)
    //    K=1024 -> tshift=4; grid.x = 16/2 = 8
    mm_h16<0><<<dim3(SEQ / BN / 2, SEQ / BM, BATCH), 128, SMEM_SZ>>>(
        pVKh + DIMD, pVKh, nullptr, pSh,
        2 * DIMD, 2 * DIMD, SEQ,
        (size_t)SEQ * 2 * DIMD, (size_t)SEQ * 2 * DIMD, (size_t)SEQ * SEQ,
        4, scale, 3);

    // 4. out = inv[row] * (P @ V)  (NN via ldsm.trans, inv in-prologue, mode 4)
    //    K=2048 -> tshift=5; grid.x = 8/2 = 4
    mm_h16<1><<<dim3(DIMD / BN / 2, SEQ / BM, BATCH), 128, SMEM_SZ>>>(
        pSh, pVKh, nullptr, out,
        SEQ, 2 * DIMD, DIMD,
        (size_t)SEQ * SEQ, (size_t)SEQ * 2 * DIMD, (size_t)SEQ * DIMD,
        5, 1.0f, 4);
}

// round 15
// speedup vs baseline: 1.1172x; 1.1172x over previous
#include <cuda_runtime.h>
#include <cuda_fp16.h>
#include <cstdint>

#define DIMD  1024
#define BATCH 8
#define SEQ   2048

// ---------------------------------------------------------------------------
// Scratch (static device memory — no allocations)
// ---------------------------------------------------------------------------
__device__ __half g_xh  [(size_t)BATCH * SEQ * DIMD];      // x fp16
__device__ __half g_Wc  [(size_t)2 * DIMD * DIMD];         // [W1;W2] fp16
__device__ float  g_bc  [2 * DIMD];                        // [b1;b2] fp32
__device__ __half g_VKh [(size_t)BATCH * SEQ * 2 * DIMD];  // cols 0-1023 V(==Q), 1024-2047 K
__device__ __half g_Sh  [(size_t)BATCH * SEQ * SEQ];       // exp(scores) fp16
__device__ float  g_ps  [(size_t)BATCH * SEQ * 32];        // partial row sums

// ---------------------------------------------------------------------------
// Helpers
// ---------------------------------------------------------------------------
__device__ __forceinline__ uint32_t smem_u32(const void* p) {
    return (uint32_t)__cvta_generic_to_shared(p);
}
// SW128 swizzle for 128-byte rows: bits[6:4] ^= bits[9:7]
__device__ __forceinline__ uint32_t swz(uint32_t o) { return o ^ ((o >> 3) & 0x70); }
// swizzle for 256-byte rows: bits[6:4] ^= bits[10:8]
__device__ __forceinline__ uint32_t swzB(uint32_t o) { return o ^ ((o >> 4) & 0x70); }

__device__ __forceinline__ void cp_async16(uint32_t dst, const void* src) {
    asm volatile("cp.async.cg.shared.global [%0], [%1], 16;" :: "r"(dst), "l"(src));
}
__device__ __forceinline__ void cp_commit() {
    asm volatile("cp.async.commit_group;" ::: "memory");
}
__device__ __forceinline__ void cp_wait1() {
    asm volatile("cp.async.wait_group 1;" ::: "memory");
}
__device__ __forceinline__ void ldsm_x4(uint32_t* r, uint32_t addr) {
    asm volatile("ldmatrix.sync.aligned.m8n8.x4.shared.b16 {%0,%1,%2,%3}, [%4];"
                 : "=r"(r[0]), "=r"(r[1]), "=r"(r[2]), "=r"(r[3]) : "r"(addr));
}
__device__ __forceinline__ void ldsm_x4_t(uint32_t* r, uint32_t addr) {
    asm volatile("ldmatrix.sync.aligned.m8n8.x4.trans.shared.b16 {%0,%1,%2,%3}, [%4];"
                 : "=r"(r[0]), "=r"(r[1]), "=r"(r[2]), "=r"(r[3]) : "r"(addr));
}
__device__ __forceinline__ void mma16816(float* c, const uint32_t* a,
                                         uint32_t b0, uint32_t b1) {
    asm volatile("mma.sync.aligned.m16n8k16.row.col.f32.f16.f16.f32 "
                 "{%0,%1,%2,%3}, {%4,%5,%6,%7}, {%8,%9}, {%0,%1,%2,%3};"
                 : "+f"(c[0]), "+f"(c[1]), "+f"(c[2]), "+f"(c[3])
                 : "r"(a[0]), "r"(a[1]), "r"(a[2]), "r"(a[3]), "r"(b0), "r"(b1));
}
// exp(x) for two halfs at once: ex2.approx.f16x2 (inputs pre-scaled by log2e)
__device__ __forceinline__ __half2 h2_ex2(__half2 x) {
    __half2 r;
    asm("ex2.approx.f16x2 %0, %1;" : "=r"(*(uint32_t*)&r) : "r"(*(const uint32_t*)&x));
    return r;
}

// ---------------------------------------------------------------------------
// fp16 tensor-core GEMM, templated on B layout:
//   TRB=0 (NT): C = alpha * A[M,K] @ B[N,K]^T
//   TRB=1 (NN): C = alpha * A[M,K] @ B[K,N]   (ldsm.trans)
// Block tile 128x128, BK=64, 3-stage cp.async ring, 128 threads (4 warps 2x2),
// warp tile 64x64, 2 CTAs/SM, register double-buffering, early global issue,
// modulo-free stage cycling, early group commit.
// mode 0: half out + fp32 bias(col).   mode 1: float out.   mode 2: half out.
// mode 3: half out = exp(alpha*acc) via f16x2 ex2, psums -> g_ps[row*32+bx*2+wn].
// mode 4: float out * rowinv; inv computed in-prologue from g_ps into smem.
// ---------------------------------------------------------------------------
#define BM 128
#define BN 128
#define BKH 64
#define STG 32768
#define NSTAGE 3
#define RING (NSTAGE * STG)
#define SMEM_SZ (RING + 512)

template<int TRB>
__global__ __launch_bounds__(128, 2)
void mm_h16(const __half* __restrict__ A, const __half* __restrict__ B,
            const float* __restrict__ aux, void* __restrict__ Cout,
            int lda, int ldb, int ldc,
            size_t zA, size_t zB, size_t zC,
            int K, float alpha, int mode)
{
    extern __shared__ char smem[];
    const uint32_t sbase = smem_u32(smem);
    float* sinv = (float*)(smem + RING);           // 128 floats (mode 4)
    const int tid = threadIdx.x;
    const int wid = tid >> 5;
    const int lane = tid & 31;

    const int bz = blockIdx.z;
    A += (size_t)bz * zA;
    B += (size_t)bz * zB;

    const int tile_m = blockIdx.y * BM;
    const int tile_n = blockIdx.x * BN;
    const int T = K / BKH;

    // --- A loader: 8 x 16B chunks per thread ---
    const int rA = tid >> 3;
    const int kcA = tid & 7;
    const __half* gA = A + (size_t)(tile_m + rA) * lda + kcA * 8;
    const uint32_t dA = swz((uint32_t)(rA * 128 + kcA * 16));

    // --- B loader ---
    const __half* gB;
    uint32_t dB;
    if (TRB == 0) {
        gB = B + (size_t)(tile_n + rA) * ldb + kcA * 8;
        dB = 16384u + swz((uint32_t)(rA * 128 + kcA * 16));
    } else {
        const int rB = tid >> 4;
        const int cB = tid & 15;
        gB = B + (size_t)rB * ldb + tile_n + cB * 8;
        dB = 16384u + swzB((uint32_t)(rB * 256 + cB * 16));
    }

// A-half and B-half of a stage load, issueable separately. soff = stage byte off.
#define LOAD_A(soff, t) do { \
        uint32_t sb_ = sbase + (soff); \
        const __half* pa_ = gA + (size_t)(t) * BKH; \
        _Pragma("unroll") \
        for (int i_ = 0; i_ < 8; i_++) \
            cp_async16(sb_ + dA + i_ * 2048u, pa_ + (size_t)(16 * i_) * lda); \
    } while (0)
#define LOAD_B(soff, t) do { \
        uint32_t sb_ = sbase + (soff); \
        if (TRB == 0) { \
            const __half* pb_ = gB + (size_t)(t) * BKH; \
            _Pragma("unroll") \
            for (int i_ = 0; i_ < 8; i_++) \
                cp_async16(sb_ + dB + i_ * 2048u, pb_ + (size_t)(16 * i_) * ldb); \
        } else { \
            const __half* pb_ = gB + (size_t)(t) * BKH * ldb; \
            _Pragma("unroll") \
            for (int i_ = 0; i_ < 8; i_++) \
                cp_async16(sb_ + dB + i_ * 2048u, pb_ + (size_t)(8 * i_) * ldb); \
        } \
    } while (0)

    #pragma unroll
    for (int p = 0; p < 2; p++) {
        if (p < T) { LOAD_A((uint32_t)p * STG, p); LOAD_B((uint32_t)p * STG, p); }
        cp_commit();
    }

    // mode 4: compute 1/rowsum for this CTA's 128 rows while cp.async streams.
    if (mode == 4) {
        const float* p = g_ps + ((size_t)(bz * SEQ + tile_m + tid)) * 32;
        float s = 0.f;
        #pragma unroll
        for (int i = 0; i < 8; i++) {
            float4 v = ((const float4*)p)[i];
            s += (v.x + v.y) + (v.z + v.w);
        }
        sinv[tid] = 1.0f / s;
    }

    // --- compute plan ---
    const int wm = wid & 1;
    const int wn = wid >> 1;
    const int lr = lane & 15;
    const int lcb = (lane >> 4) * 16;

    uint32_t aoff0[4], boff0[4];
    #pragma unroll
    for (int mi = 0; mi < 4; mi++)
        aoff0[mi] = swz((uint32_t)((wm * 64 + mi * 16 + lr) * 128 + lcb));
    if (TRB == 0) {
        #pragma unroll
        for (int nb = 0; nb < 4; nb++)
            boff0[nb] = 16384u + swz((uint32_t)((wn * 64 + nb * 16 + lr) * 128 + lcb));
    } else {
        #pragma unroll
        for (int nb = 0; nb < 4; nb++)
            boff0[nb] = 16384u + swzB((uint32_t)(lr * 256 + wn * 128 + nb * 32 + lcb));
    }

#define LDFRAG(af, bf, sa_, ks_) do { \
        _Pragma("unroll") \
        for (int mi_ = 0; mi_ < 4; mi_++) \
            ldsm_x4((af)[mi_], (sa_) + (aoff0[mi_] ^ (uint32_t)((ks_) * 32))); \
        if (TRB == 0) { \
            _Pragma("unroll") \
            for (int nb_ = 0; nb_ < 4; nb_++) \
                ldsm_x4((bf)[nb_], (sa_) + (boff0[nb_] ^ (uint32_t)((ks_) * 32))); \
        } else { \
            _Pragma("unroll") \
            for (int nb_ = 0; nb_ < 4; nb_++) \
                ldsm_x4_t((bf)[nb_], (sa_) + boff0[nb_] + (uint32_t)((ks_) * 4096)); \
        } \
    } while (0)

#define MMABLK(af, bf) do { \
        _Pragma("unroll") \
        for (int mi_ = 0; mi_ < 4; mi_++) \
            _Pragma("unroll") \
            for (int ni_ = 0; ni_ < 8; ni_++) { \
                uint32_t b0_ = (TRB == 0) ? (bf)[ni_ >> 1][ni_ & 1] \
                                          : (bf)[ni_ >> 1][(ni_ & 1) * 2]; \
                uint32_t b1_ = (TRB == 0) ? (bf)[ni_ >> 1][(ni_ & 1) + 2] \
                                          : (bf)[ni_ >> 1][(ni_ & 1) * 2 + 1]; \
                mma16816(acc[mi_][ni_], (af)[mi_], b0_, b1_); \
            } \
    } while (0)

    float acc[4][8][4] = {};
    uint32_t a0[4][4], b0[4][4], a1[4][4], b1[4][4];

    cp_wait1();
    __syncthreads();
    LDFRAG(a0, b0, sbase, 0);

    // Modulo-free cyclic stage offsets: cur (compute), pre (prefetch target).
    uint32_t cur = 0;                  // stage t % 3, in bytes
    uint32_t pre = 2u * STG;           // stage (t+2) % 3, in bytes

    for (int t = 0; t < T; t++) {
        const uint32_t sa = sbase + cur;
        const bool pf = (t + 2 < T);

        LDFRAG(a1, b1, sa, 1);
        MMABLK(a0, b0);                // ks 0
        if (pf) LOAD_A(pre, t + 2);    // issue global loads early, mid-compute
        LDFRAG(a0, b0, sa, 2);
        MMABLK(a1, b1);                // ks 1
        if (pf) LOAD_B(pre, t + 2);
        cp_commit();                   // close group early -> retires sooner
        LDFRAG(a1, b1, sa, 3);
        MMABLK(a0, b0);                // ks 2

        cp_wait1();
        __syncthreads();

        cur += STG; if (cur == RING) cur = 0;
        pre += STG; if (pre == RING) pre = 0;

        if (t + 1 < T)
            LDFRAG(a0, b0, sbase + cur, 0);
        MMABLK(a1, b1);                // ks 3 (covers barrier + next-stage loads)
    }

    // --- epilogue ---
    const int er = lane >> 2;
    const int ec = (lane & 3) * 2;

    if (mode == 1 || mode == 4) {
        float* C = (float*)Cout + (size_t)bz * zC;
        #pragma unroll
        for (int mi = 0; mi < 4; mi++) {
            int mrow = wm * 64 + mi * 16 + er;
            int m0 = tile_m + mrow;
            float s0 = alpha, s1 = alpha;
            if (mode == 4) { s0 = sinv[mrow]; s1 = sinv[mrow + 8]; }
            #pragma unroll
            for (int ni = 0; ni < 8; ni++) {
                int n0 = tile_n + wn * 64 + ni * 8 + ec;
                float* c = acc[mi][ni];
                *(float2*)(C + (size_t)m0 * ldc + n0) =
                    make_float2(c[0] * s0, c[1] * s0);
                *(float2*)(C + (size_t)(m0 + 8) * ldc + n0) =
                    make_float2(c[2] * s1, c[3] * s1);
            }
        }
    } else {
        __half* C = (__half*)Cout + (size_t)bz * zC;
        float psum[4][2];
        #pragma unroll
        for (int mi = 0; mi < 4; mi++) { psum[mi][0] = 0.f; psum[mi][1] = 0.f; }

        const float l2e_alpha = alpha * 1.4426950408889634f;  // alpha * log2(e)

        #pragma unroll
        for (int mi = 0; mi < 4; mi++) {
            #pragma unroll
            for (int ni = 0; ni < 8; ni++) {
                int m0 = tile_m + wm * 64 + mi * 16 + er;
                int n0 = tile_n + wn * 64 + ni * 8 + ec;
                float* c = acc[mi][ni];
                __half2 h01, h23;
                if (mode == 3) {
                    h01 = h2_ex2(__floats2half2_rn(c[0] * l2e_alpha, c[1] * l2e_alpha));
                    h23 = h2_ex2(__floats2half2_rn(c[2] * l2e_alpha, c[3] * l2e_alpha));
                    float2 f01 = __half22float2(h01);
                    float2 f23 = __half22float2(h23);
                    psum[mi][0] += f01.x + f01.y;
                    psum[mi][1] += f23.x + f23.y;
                } else {
                    float bx = 0.f, by = 0.f;
                    if (mode == 0) { bx = aux[n0]; by = aux[n0 + 1]; }
                    h01 = __floats2half2_rn(c[0] * alpha + bx, c[1] * alpha + by);
                    h23 = __floats2half2_rn(c[2] * alpha + bx, c[3] * alpha + by);
                }
                *(__half2*)(C + (size_t)m0 * ldc + n0) = h01;
                *(__half2*)(C + (size_t)(m0 + 8) * ldc + n0) = h23;
            }
        }

        if (mode == 3) {
            #pragma unroll
            for (int mi = 0; mi < 4; mi++) {
                #pragma unroll
                for (int h = 0; h < 2; h++) {
                    float v = psum[mi][h];
                    v += __shfl_xor_sync(0xffffffffu, v, 1);
                    v += __shfl_xor_sync(0xffffffffu, v, 2);
                    if ((lane & 3) == 0) {
                        int row = bz * SEQ + tile_m + wm * 64 + mi * 16 + er + h * 8;
                        g_ps[(size_t)row * 32 + blockIdx.x * 2 + wn] = v;
                    }
                }
            }
        }
    }
#undef LOAD_A
#undef LOAD_B
#undef LDFRAG
#undef MMABLK
}

// ---------------------------------------------------------------------------
// Combined prep: xh = fp16(x), Wc = fp16([W1;W2]), bc = [b1;b2]
// ---------------------------------------------------------------------------
__global__ __launch_bounds__(256)
void prep_all(const float* __restrict__ x,
              const float* __restrict__ W1, const float* __restrict__ W2,
              const float* __restrict__ b1, const float* __restrict__ b2,
              __half* __restrict__ xh, __half* __restrict__ Wc,
              float* __restrict__ bc)
{
    const long long nx4 = (long long)BATCH * SEQ * DIMD / 4;
    const long long nw4 = (long long)DIMD * DIMD / 4;
    long long i = (long long)blockIdx.x * blockDim.x + threadIdx.x;
    long long stride = (long long)gridDim.x * blockDim.x;

    for (long long j = i; j < nx4; j += stride) {
        float4 v = ((const float4*)x)[j];
        ((__half2*)xh)[2 * j + 0] = __floats2half2_rn(v.x, v.y);
        ((__half2*)xh)[2 * j + 1] = __floats2half2_rn(v.z, v.w);
    }
    for (long long j = i; j < 2 * nw4; j += stride) {
        const float* src = (j < nw4) ? W1 : W2;
        long long k = (j < nw4) ? j : j - nw4;
        float4 v = ((const float4*)src)[k];
        ((__half2*)Wc)[2 * j + 0] = __floats2half2_rn(v.x, v.y);
        ((__half2*)Wc)[2 * j + 1] = __floats2half2_rn(v.z, v.w);
    }
    for (long long j = i; j < 2 * DIMD; j += stride)
        bc[j] = (j < DIMD) ? b1[j] : b2[j - DIMD];
}

// ---------------------------------------------------------------------------
// Launch
// ---------------------------------------------------------------------------
extern "C" void kernel_launch(void* const* d_in, const int* in_sizes, int n_in,
                              void* d_out, int out_size)
{
    const float* x  = (const float*)d_in[0];
    const float* W1 = (const float*)d_in[1];
    const float* b1 = (const float*)d_in[2];
    const float* W2 = (const float*)d_in[3];
    const float* b2 = (const float*)d_in[4];
    float* out = (float*)d_out;

    __half *pxh, *pWc, *pVKh, *pSh;
    float *pbc;
    cudaGetSymbolAddress((void**)&pxh,  g_xh);
    cudaGetSymbolAddress((void**)&pWc,  g_Wc);
    cudaGetSymbolAddress((void**)&pbc,  g_bc);
    cudaGetSymbolAddress((void**)&pVKh, g_VKh);
    cudaGetSymbolAddress((void**)&pSh,  g_Sh);

    cudaFuncSetAttribute(mm_h16<0>, cudaFuncAttributeMaxDynamicSharedMemorySize, SMEM_SZ);
    cudaFuncSetAttribute(mm_h16<1>, cudaFuncAttributeMaxDynamicSharedMemorySize, SMEM_SZ);

    const float scale = 1.0f / 32.0f;  // 1/sqrt(1024)

    // 1. fp32 -> fp16 inputs/weights/biases (one kernel)
    prep_all<<<2048, 256>>>(x, W1, W2, b1, b2, pxh, pWc, pbc);

    // 2. [V | K] = fp16(x @ [W1;W2]^T + [b1;b2]) : M=16384, N=2048, K=1024 (NT)
    mm_h16<0><<<dim3(2 * DIMD / BN, BATCH * SEQ / BM, 1), 128, SMEM_SZ>>>(
        pxh, pWc, pbc, pVKh,
        DIMD, DIMD, 2 * DIMD, 0, 0, 0,
        DIMD, 1.0f, 0);

    // 3. P = fp16(exp(scale * K . V)) + partial row sums (NT, mode 3)
    mm_h16<0><<<dim3(SEQ / BN, SEQ / BM, BATCH), 128, SMEM_SZ>>>(
        pVKh + DIMD, pVKh, nullptr, pSh,
        2 * DIMD, 2 * DIMD, SEQ,
        (size_t)SEQ * 2 * DIMD, (size_t)SEQ * 2 * DIMD, (size_t)SEQ * SEQ,
        DIMD, scale, 3);

    // 4. out = inv[row] * (P @ V)  (NN via ldsm.trans, inv in-prologue, mode 4)
    mm_h16<1><<<dim3(DIMD / BN, SEQ / BM, BATCH), 128, SMEM_SZ>>>(
        pSh, pVKh, nullptr, out,
        SEQ, 2 * DIMD, DIMD,
        (size_t)SEQ * SEQ, (size_t)SEQ * 2 * DIMD, (size_t)SEQ * DIMD,
        SEQ, 1.0f, 4);
}

// round 16
// speedup vs baseline: 1.1316x; 1.0129x over previous
#include <cuda_runtime.h>
#include <cuda_fp16.h>
#include <cstdint>

#define DIMD  1024
#define BATCH 8
#define SEQ   2048

// ---------------------------------------------------------------------------
// Scratch (static device memory — no allocations)
// ---------------------------------------------------------------------------
__device__ __half g_xh  [(size_t)BATCH * SEQ * DIMD];      // x fp16
__device__ __half g_Wc  [(size_t)2 * DIMD * DIMD];         // [W1;W2] fp16
__device__ float  g_bc  [2 * DIMD];                        // [b1;b2] fp32
__device__ __half g_VKh [(size_t)BATCH * SEQ * 2 * DIMD];  // cols 0-1023 V(==Q), 1024-2047 K
__device__ __half g_Sh  [(size_t)BATCH * SEQ * SEQ];       // exp(scores) fp16
__device__ float  g_ps  [(size_t)BATCH * SEQ * 32];        // partial row sums

// ---------------------------------------------------------------------------
// Helpers
// ---------------------------------------------------------------------------
__device__ __forceinline__ uint32_t smem_u32(const void* p) {
    return (uint32_t)__cvta_generic_to_shared(p);
}
// SW128 swizzle for 128-byte rows: bits[6:4] ^= bits[9:7]
__device__ __forceinline__ uint32_t swz(uint32_t o) { return o ^ ((o >> 3) & 0x70); }
// swizzle for 256-byte rows: bits[6:4] ^= bits[10:8]
__device__ __forceinline__ uint32_t swzB(uint32_t o) { return o ^ ((o >> 4) & 0x70); }

__device__ __forceinline__ void cp_async16(uint32_t dst, const void* src) {
    asm volatile("cp.async.cg.shared.global [%0], [%1], 16;" :: "r"(dst), "l"(src));
}
__device__ __forceinline__ void cp_commit() {
    asm volatile("cp.async.commit_group;" ::: "memory");
}
__device__ __forceinline__ void cp_wait1() {
    asm volatile("cp.async.wait_group 1;" ::: "memory");
}
__device__ __forceinline__ void ldsm_x4(uint32_t* r, uint32_t addr) {
    asm volatile("ldmatrix.sync.aligned.m8n8.x4.shared.b16 {%0,%1,%2,%3}, [%4];"
                 : "=r"(r[0]), "=r"(r[1]), "=r"(r[2]), "=r"(r[3]) : "r"(addr));
}
__device__ __forceinline__ void ldsm_x4_t(uint32_t* r, uint32_t addr) {
    asm volatile("ldmatrix.sync.aligned.m8n8.x4.trans.shared.b16 {%0,%1,%2,%3}, [%4];"
                 : "=r"(r[0]), "=r"(r[1]), "=r"(r[2]), "=r"(r[3]) : "r"(addr));
}
__device__ __forceinline__ void mma16816(float* c, const uint32_t* a,
                                         uint32_t b0, uint32_t b1) {
    asm volatile("mma.sync.aligned.m16n8k16.row.col.f32.f16.f16.f32 "
                 "{%0,%1,%2,%3}, {%4,%5,%6,%7}, {%8,%9}, {%0,%1,%2,%3};"
                 : "+f"(c[0]), "+f"(c[1]), "+f"(c[2]), "+f"(c[3])
                 : "r"(a[0]), "r"(a[1]), "r"(a[2]), "r"(a[3]), "r"(b0), "r"(b1));
}
// exp(x) for two halfs at once: ex2.approx.f16x2 (inputs pre-scaled by log2e)
__device__ __forceinline__ __half2 h2_ex2(__half2 x) {
    __half2 r;
    asm("ex2.approx.f16x2 %0, %1;" : "=r"(*(uint32_t*)&r) : "r"(*(const uint32_t*)&x));
    return r;
}

// ---------------------------------------------------------------------------
// fp16 tensor-core GEMM, templated on B layout:
//   TRB=0 (NT): C = alpha * A[M,K] @ B[N,K]^T
//   TRB=1 (NN): C = alpha * A[M,K] @ B[K,N]   (ldsm.trans)
// Block tile 128x128, BK=64, 3-stage cp.async ring, 128 threads (4 warps 2x2),
// warp tile 64x64, 2 CTAs/SM, register double-buffering, early global issue.
// mode 0: half out + fp32 bias(col), bias preloaded to smem in prologue.
// mode 1: float out.   mode 2: half out.
// mode 3: half out = exp(alpha*acc) via f16x2 ex2, psums -> g_ps[row*32+bx*2+wn].
// mode 4: float out * rowinv; inv computed in-prologue from g_ps into smem.
// ---------------------------------------------------------------------------
#define BM 128
#define BN 128
#define BKH 64
#define STG 32768
#define NSTAGE 3
#define RING (NSTAGE * STG)
#define SMEM_SZ (RING + 512)

template<int TRB>
__global__ __launch_bounds__(128, 2)
void mm_h16(const __half* __restrict__ A, const __half* __restrict__ B,
            const float* __restrict__ aux, void* __restrict__ Cout,
            int lda, int ldb, int ldc,
            size_t zA, size_t zB, size_t zC,
            int K, float alpha, int mode)
{
    extern __shared__ char smem[];
    const uint32_t sbase = smem_u32(smem);
    float* saux = (float*)(smem + RING);   // 128 floats: inv (mode 4) or bias (mode 0)
    const int tid = threadIdx.x;
    const int wid = tid >> 5;
    const int lane = tid & 31;

    const int bz = blockIdx.z;
    A += (size_t)bz * zA;
    B += (size_t)bz * zB;

    const int tile_m = blockIdx.y * BM;
    const int tile_n = blockIdx.x * BN;
    const int T = K / BKH;

    // --- A loader: 8 x 16B chunks per thread ---
    const int rA = tid >> 3;
    const int kcA = tid & 7;
    const __half* gA = A + (size_t)(tile_m + rA) * lda + kcA * 8;
    const uint32_t dA = swz((uint32_t)(rA * 128 + kcA * 16));

    // --- B loader ---
    const __half* gB;
    uint32_t dB;
    if (TRB == 0) {
        gB = B + (size_t)(tile_n + rA) * ldb + kcA * 8;
        dB = 16384u + swz((uint32_t)(rA * 128 + kcA * 16));
    } else {
        const int rB = tid >> 4;
        const int cB = tid & 15;
        gB = B + (size_t)rB * ldb + tile_n + cB * 8;
        dB = 16384u + swzB((uint32_t)(rB * 256 + cB * 16));
    }

// A-half and B-half of a stage load, issueable separately.
#define LOAD_A(s, t) do { \
        uint32_t sb_ = sbase + (uint32_t)(s) * STG; \
        const __half* pa_ = gA + (size_t)(t) * BKH; \
        _Pragma("unroll") \
        for (int i_ = 0; i_ < 8; i_++) \
            cp_async16(sb_ + dA + i_ * 2048u, pa_ + (size_t)(16 * i_) * lda); \
    } while (0)
#define LOAD_B(s, t) do { \
        uint32_t sb_ = sbase + (uint32_t)(s) * STG; \
        if (TRB == 0) { \
            const __half* pb_ = gB + (size_t)(t) * BKH; \
            _Pragma("unroll") \
            for (int i_ = 0; i_ < 8; i_++) \
                cp_async16(sb_ + dB + i_ * 2048u, pb_ + (size_t)(16 * i_) * ldb); \
        } else { \
            const __half* pb_ = gB + (size_t)(t) * BKH * ldb; \
            _Pragma("unroll") \
            for (int i_ = 0; i_ < 8; i_++) \
                cp_async16(sb_ + dB + i_ * 2048u, pb_ + (size_t)(8 * i_) * ldb); \
        } \
    } while (0)

    #pragma unroll
    for (int p = 0; p < 2; p++) {
        if (p < T) { LOAD_A(p, p); LOAD_B(p, p); }
        cp_commit();
    }

    // Prologue side-work (hidden under cp.async stage fill):
    // mode 4: 1/rowsum for this CTA's 128 rows.
    // mode 0: preload this tile's 128 bias values to smem.
    if (mode == 4) {
        const float* p = g_ps + ((size_t)(bz * SEQ + tile_m + tid)) * 32;
        float s = 0.f;
        #pragma unroll
        for (int i = 0; i < 8; i++) {
            float4 v = ((const float4*)p)[i];
            s += (v.x + v.y) + (v.z + v.w);
        }
        saux[tid] = 1.0f / s;
    } else if (mode == 0) {
        saux[tid] = aux[tile_n + tid];
    }

    // --- compute plan ---
    const int wm = wid & 1;
    const int wn = wid >> 1;
    const int lr = lane & 15;
    const int lcb = (lane >> 4) * 16;

    uint32_t aoff0[4], boff0[4];
    #pragma unroll
    for (int mi = 0; mi < 4; mi++)
        aoff0[mi] = swz((uint32_t)((wm * 64 + mi * 16 + lr) * 128 + lcb));
    if (TRB == 0) {
        #pragma unroll
        for (int nb = 0; nb < 4; nb++)
            boff0[nb] = 16384u + swz((uint32_t)((wn * 64 + nb * 16 + lr) * 128 + lcb));
    } else {
        #pragma unroll
        for (int nb = 0; nb < 4; nb++)
            boff0[nb] = 16384u + swzB((uint32_t)(lr * 256 + wn * 128 + nb * 32 + lcb));
    }

#define LDFRAG(af, bf, sa_, ks_) do { \
        _Pragma("unroll") \
        for (int mi_ = 0; mi_ < 4; mi_++) \
            ldsm_x4((af)[mi_], (sa_) + (aoff0[mi_] ^ (uint32_t)((ks_) * 32))); \
        if (TRB == 0) { \
            _Pragma("unroll") \
            for (int nb_ = 0; nb_ < 4; nb_++) \
                ldsm_x4((bf)[nb_], (sa_) + (boff0[nb_] ^ (uint32_t)((ks_) * 32))); \
        } else { \
            _Pragma("unroll") \
            for (int nb_ = 0; nb_ < 4; nb_++) \
                ldsm_x4_t((bf)[nb_], (sa_) + boff0[nb_] + (uint32_t)((ks_) * 4096)); \
        } \
    } while (0)

#define MMABLK(af, bf) do { \
        _Pragma("unroll") \
        for (int mi_ = 0; mi_ < 4; mi_++) \
            _Pragma("unroll") \
            for (int ni_ = 0; ni_ < 8; ni_++) { \
                uint32_t b0_ = (TRB == 0) ? (bf)[ni_ >> 1][ni_ & 1] \
                                          : (bf)[ni_ >> 1][(ni_ & 1) * 2]; \
                uint32_t b1_ = (TRB == 0) ? (bf)[ni_ >> 1][(ni_ & 1) + 2] \
                                          : (bf)[ni_ >> 1][(ni_ & 1) * 2 + 1]; \
                mma16816(acc[mi_][ni_], (af)[mi_], b0_, b1_); \
            } \
    } while (0)

    float acc[4][8][4] = {};
    uint32_t a0[4][4], b0[4][4], a1[4][4], b1[4][4];

    cp_wait1();
    __syncthreads();
    LDFRAG(a0, b0, sbase, 0);

    for (int t = 0; t < T; t++) {
        const uint32_t sa = sbase + (uint32_t)(t % NSTAGE) * STG;
        const bool pf = (t + 2 < T);
        const int ps = (t + 2) % NSTAGE;

        LDFRAG(a1, b1, sa, 1);
        MMABLK(a0, b0);                // ks 0
        if (pf) LOAD_A(ps, t + 2);     // issue global loads early, mid-compute
        LDFRAG(a0, b0, sa, 2);
        MMABLK(a1, b1);                // ks 1
        if (pf) LOAD_B(ps, t + 2);
        LDFRAG(a1, b1, sa, 3);
        MMABLK(a0, b0);                // ks 2

        cp_commit();
        cp_wait1();
        __syncthreads();

        if (t + 1 < T)
            LDFRAG(a0, b0, sbase + (uint32_t)((t + 1) % NSTAGE) * STG, 0);
        MMABLK(a1, b1);                // ks 3 (covers barrier + next-stage loads)
    }

    // --- epilogue ---
    const int er = lane >> 2;
    const int ec = (lane & 3) * 2;

    if (mode == 1 || mode == 4) {
        float* C = (float*)Cout + (size_t)bz * zC;
        #pragma unroll
        for (int mi = 0; mi < 4; mi++) {
            int mrow = wm * 64 + mi * 16 + er;
            int m0 = tile_m + mrow;
            float s0 = alpha, s1 = alpha;
            if (mode == 4) { s0 = saux[mrow]; s1 = saux[mrow + 8]; }
            #pragma unroll
            for (int ni = 0; ni < 8; ni++) {
                int n0 = tile_n + wn * 64 + ni * 8 + ec;
                float* c = acc[mi][ni];
                *(float2*)(C + (size_t)m0 * ldc + n0) =
                    make_float2(c[0] * s0, c[1] * s0);
                *(float2*)(C + (size_t)(m0 + 8) * ldc + n0) =
                    make_float2(c[2] * s1, c[3] * s1);
            }
        }
    } else {
        __half* C = (__half*)Cout + (size_t)bz * zC;
        float psum[4][2];
        #pragma unroll
        for (int mi = 0; mi < 4; mi++) { psum[mi][0] = 0.f; psum[mi][1] = 0.f; }

        const float l2e_alpha = alpha * 1.4426950408889634f;  // alpha * log2(e)

        #pragma unroll
        for (int mi = 0; mi < 4; mi++) {
            #pragma unroll
            for (int ni = 0; ni < 8; ni++) {
                int m0 = tile_m + wm * 64 + mi * 16 + er;
                int nl = wn * 64 + ni * 8 + ec;        // local n within tile
                int n0 = tile_n + nl;
                float* c = acc[mi][ni];
                __half2 h01, h23;
                if (mode == 3) {
                    h01 = h2_ex2(__floats2half2_rn(c[0] * l2e_alpha, c[1] * l2e_alpha));
                    h23 = h2_ex2(__floats2half2_rn(c[2] * l2e_alpha, c[3] * l2e_alpha));
                    float2 f01 = __half22float2(h01);
                    float2 f23 = __half22float2(h23);
                    psum[mi][0] += f01.x + f01.y;
                    psum[mi][1] += f23.x + f23.y;
                } else {
                    float bx = 0.f, by = 0.f;
                    if (mode == 0) { bx = saux[nl]; by = saux[nl + 1]; }
                    h01 = __floats2half2_rn(c[0] * alpha + bx, c[1] * alpha + by);
                    h23 = __floats2half2_rn(c[2] * alpha + bx, c[3] * alpha + by);
                }
                *(__half2*)(C + (size_t)m0 * ldc + n0) = h01;
                *(__half2*)(C + (size_t)(m0 + 8) * ldc + n0) = h23;
            }
        }

        if (mode == 3) {
            #pragma unroll
            for (int mi = 0; mi < 4; mi++) {
                #pragma unroll
                for (int h = 0; h < 2; h++) {
                    float v = psum[mi][h];
                    v += __shfl_xor_sync(0xffffffffu, v, 1);
                    v += __shfl_xor_sync(0xffffffffu, v, 2);
                    if ((lane & 3) == 0) {
                        int row = bz * SEQ + tile_m + wm * 64 + mi * 16 + er + h * 8;
                        g_ps[(size_t)row * 32 + blockIdx.x * 2 + wn] = v;
                    }
                }
            }
        }
    }
#undef LOAD_A
#undef LOAD_B
#undef LDFRAG
#undef MMABLK
}

// ---------------------------------------------------------------------------
// Combined prep: xh = fp16(x), Wc = fp16([W1;W2]), bc = [b1;b2]
// ---------------------------------------------------------------------------
__global__ __launch_bounds__(256)
void prep_all(const float* __restrict__ x,
              const float* __restrict__ W1, const float* __restrict__ W2,
              const float* __restrict__ b1, const float* __restrict__ b2,
              __half* __restrict__ xh, __half* __restrict__ Wc,
              float* __restrict__ bc)
{
    const long long nx4 = (long long)BATCH * SEQ * DIMD / 4;
    const long long nw4 = (long long)DIMD * DIMD / 4;
    long long i = (long long)blockIdx.x * blockDim.x + threadIdx.x;
    long long stride = (long long)gridDim.x * blockDim.x;

    for (long long j = i; j < nx4; j += stride) {
        float4 v = ((const float4*)x)[j];
        ((__half2*)xh)[2 * j + 0] = __floats2half2_rn(v.x, v.y);
        ((__half2*)xh)[2 * j + 1] = __floats2half2_rn(v.z, v.w);
    }
    for (long long j = i; j < 2 * nw4; j += stride) {
        const float* src = (j < nw4) ? W1 : W2;
        long long k = (j < nw4) ? j : j - nw4;
        float4 v = ((const float4*)src)[k];
        ((__half2*)Wc)[2 * j + 0] = __floats2half2_rn(v.x, v.y);
        ((__half2*)Wc)[2 * j + 1] = __floats2half2_rn(v.z, v.w);
    }
    for (long long j = i; j < 2 * DIMD; j += stride)
        bc[j] = (j < DIMD) ? b1[j] : b2[j - DIMD];
}

// ---------------------------------------------------------------------------
// Launch
// ---------------------------------------------------------------------------
extern "C" void kernel_launch(void* const* d_in, const int* in_sizes, int n_in,
                              void* d_out, int out_size)
{
    const float* x  = (const float*)d_in[0];
    const float* W1 = (const float*)d_in[1];
    const float* b1 = (const float*)d_in[2];
    const float* W2 = (const float*)d_in[3];
    const float* b2 = (const float*)d_in[4];
    float* out = (float*)d_out;

    __half *pxh, *pWc, *pVKh, *pSh;
    float *pbc;
    cudaGetSymbolAddress((void**)&pxh,  g_xh);
    cudaGetSymbolAddress((void**)&pWc,  g_Wc);
    cudaGetSymbolAddress((void**)&pbc,  g_bc);
    cudaGetSymbolAddress((void**)&pVKh, g_VKh);
    cudaGetSymbolAddress((void**)&pSh,  g_Sh);

    cudaFuncSetAttribute(mm_h16<0>, cudaFuncAttributeMaxDynamicSharedMemorySize, SMEM_SZ);
    cudaFuncSetAttribute(mm_h16<1>, cudaFuncAttributeMaxDynamicSharedMemorySize, SMEM_SZ);

    const float scale = 1.0f / 32.0f;  // 1/sqrt(1024)

    // 1. fp32 -> fp16 inputs/weights/biases (one kernel)
    prep_all<<<2048, 256>>>(x, W1, W2, b1, b2, pxh, pWc, pbc);

    // 2. [V | K] = fp16(x @ [W1;W2]^T + [b1;b2]) : M=16384, N=2048, K=1024 (NT)
    mm_h16<0><<<dim3(2 * DIMD / BN, BATCH * SEQ / BM, 1), 128, SMEM_SZ>>>(
        pxh, pWc, pbc, pVKh,
        DIMD, DIMD, 2 * DIMD, 0, 0, 0,
        DIMD, 1.0f, 0);

    // 3. P = fp16(exp(scale * K . V)) + partial row sums (NT, mode 3)
    mm_h16<0><<<dim3(SEQ / BN, SEQ / BM, BATCH), 128, SMEM_SZ>>>(
        pVKh + DIMD, pVKh, nullptr, pSh,
        2 * DIMD, 2 * DIMD, SEQ,
        (size_t)SEQ * 2 * DIMD, (size_t)SEQ * 2 * DIMD, (size_t)SEQ * SEQ,
        DIMD, scale, 3);

    // 4. out = inv[row] * (P @ V)  (NN via ldsm.trans, inv in-prologue, mode 4)
    mm_h16<1><<<dim3(DIMD / BN, SEQ / BM, BATCH), 128, SMEM_SZ>>>(
        pSh, pVKh, nullptr, out,
        SEQ, 2 * DIMD, DIMD,
        (size_t)SEQ * SEQ, (size_t)SEQ * 2 * DIMD, (size_t)SEQ * DIMD,
        SEQ, 1.0f, 4);
}

// round 17
// speedup vs baseline: 1.1437x; 1.0107x over previous
#include <cuda_runtime.h>
#include <cuda_fp16.h>
#include <cstdint>

#define DIMD  1024
#define BATCH 8
#define SEQ   2048

// ---------------------------------------------------------------------------
// Scratch (static device memory — no allocations)
// ---------------------------------------------------------------------------
__device__ __half g_xh  [(size_t)BATCH * SEQ * DIMD];      // x fp16
__device__ __half g_Wc  [(size_t)2 * DIMD * DIMD];         // [W1;W2] fp16
__device__ float  g_bc  [2 * DIMD];                        // [b1;b2] fp32
__device__ __half g_VKh [(size_t)BATCH * SEQ * 2 * DIMD];  // cols 0-1023 V(==Q), 1024-2047 K
__device__ __half g_Sh  [(size_t)BATCH * SEQ * SEQ];       // exp(scores) fp16
__device__ float  g_ps  [(size_t)BATCH * SEQ * 32];        // partial row sums

// ---------------------------------------------------------------------------
// Helpers
// ---------------------------------------------------------------------------
__device__ __forceinline__ uint32_t smem_u32(const void* p) {
    return (uint32_t)__cvta_generic_to_shared(p);
}
// SW128 swizzle for 128-byte rows: bits[6:4] ^= bits[9:7]
__device__ __forceinline__ uint32_t swz(uint32_t o) { return o ^ ((o >> 3) & 0x70); }
// swizzle for 256-byte rows: bits[6:4] ^= bits[10:8]
__device__ __forceinline__ uint32_t swzB(uint32_t o) { return o ^ ((o >> 4) & 0x70); }

__device__ __forceinline__ void cp_async16(uint32_t dst, const void* src) {
    asm volatile("cp.async.cg.shared.global [%0], [%1], 16;" :: "r"(dst), "l"(src));
}
__device__ __forceinline__ void cp_commit() {
    asm volatile("cp.async.commit_group;" ::: "memory");
}
__device__ __forceinline__ void cp_wait1() {
    asm volatile("cp.async.wait_group 1;" ::: "memory");
}
__device__ __forceinline__ void ldsm_x4(uint32_t* r, uint32_t addr) {
    asm volatile("ldmatrix.sync.aligned.m8n8.x4.shared.b16 {%0,%1,%2,%3}, [%4];"
                 : "=r"(r[0]), "=r"(r[1]), "=r"(r[2]), "=r"(r[3]) : "r"(addr));
}
__device__ __forceinline__ void ldsm_x4_t(uint32_t* r, uint32_t addr) {
    asm volatile("ldmatrix.sync.aligned.m8n8.x4.trans.shared.b16 {%0,%1,%2,%3}, [%4];"
                 : "=r"(r[0]), "=r"(r[1]), "=r"(r[2]), "=r"(r[3]) : "r"(addr));
}
__device__ __forceinline__ void mma16816(float* c, const uint32_t* a,
                                         uint32_t b0, uint32_t b1) {
    asm volatile("mma.sync.aligned.m16n8k16.row.col.f32.f16.f16.f32 "
                 "{%0,%1,%2,%3}, {%4,%5,%6,%7}, {%8,%9}, {%0,%1,%2,%3};"
                 : "+f"(c[0]), "+f"(c[1]), "+f"(c[2]), "+f"(c[3])
                 : "r"(a[0]), "r"(a[1]), "r"(a[2]), "r"(a[3]), "r"(b0), "r"(b1));
}
// exp(x) for two halfs at once: ex2.approx.f16x2 (inputs pre-scaled by log2e)
__device__ __forceinline__ __half2 h2_ex2(__half2 x) {
    __half2 r;
    asm("ex2.approx.f16x2 %0, %1;" : "=r"(*(uint32_t*)&r) : "r"(*(const uint32_t*)&x));
    return r;
}

// ---------------------------------------------------------------------------
// fp16 tensor-core GEMM, templated on B layout:
//   TRB=0 (NT): C = alpha * A[M,K] @ B[N,K]^T
//   TRB=1 (NN): C = alpha * A[M,K] @ B[K,N]   (ldsm.trans)
// Block tile 128x128, BK=64, 3-stage cp.async ring, 128 threads (4 warps 2x2),
// warp tile 64x64, 2 CTAs/SM, register double-buffering, early global issue.
// Mainloop drains ALL MMA work before the barrier (ks3 moved ahead of wait).
// mode 0: half out + fp32 bias(col), bias preloaded to smem in prologue.
// mode 1: float out.   mode 2: half out.
// mode 3: half out = exp(alpha*acc) via f16x2 ex2, psums -> g_ps[row*32+bx*2+wn].
// mode 4: float out * rowinv; inv computed in-prologue from g_ps into smem.
// ---------------------------------------------------------------------------
#define BM 128
#define BN 128
#define BKH 64
#define STG 32768
#define NSTAGE 3
#define RING (NSTAGE * STG)
#define SMEM_SZ (RING + 512)

template<int TRB>
__global__ __launch_bounds__(128, 2)
void mm_h16(const __half* __restrict__ A, const __half* __restrict__ B,
            const float* __restrict__ aux, void* __restrict__ Cout,
            int lda, int ldb, int ldc,
            size_t zA, size_t zB, size_t zC,
            int K, float alpha, int mode)
{
    extern __shared__ char smem[];
    const uint32_t sbase = smem_u32(smem);
    float* saux = (float*)(smem + RING);   // 128 floats: inv (mode 4) or bias (mode 0)
    const int tid = threadIdx.x;
    const int wid = tid >> 5;
    const int lane = tid & 31;

    const int bz = blockIdx.z;
    A += (size_t)bz * zA;
    B += (size_t)bz * zB;

    const int tile_m = blockIdx.y * BM;
    const int tile_n = blockIdx.x * BN;
    const int T = K / BKH;

    // --- A loader: 8 x 16B chunks per thread ---
    const int rA = tid >> 3;
    const int kcA = tid & 7;
    const __half* gA = A + (size_t)(tile_m + rA) * lda + kcA * 8;
    const uint32_t dA = swz((uint32_t)(rA * 128 + kcA * 16));

    // --- B loader ---
    const __half* gB;
    uint32_t dB;
    if (TRB == 0) {
        gB = B + (size_t)(tile_n + rA) * ldb + kcA * 8;
        dB = 16384u + swz((uint32_t)(rA * 128 + kcA * 16));
    } else {
        const int rB = tid >> 4;
        const int cB = tid & 15;
        gB = B + (size_t)rB * ldb + tile_n + cB * 8;
        dB = 16384u + swzB((uint32_t)(rB * 256 + cB * 16));
    }

// A-half and B-half of a stage load, issueable separately.
#define LOAD_A(s, t) do { \
        uint32_t sb_ = sbase + (uint32_t)(s) * STG; \
        const __half* pa_ = gA + (size_t)(t) * BKH; \
        _Pragma("unroll") \
        for (int i_ = 0; i_ < 8; i_++) \
            cp_async16(sb_ + dA + i_ * 2048u, pa_ + (size_t)(16 * i_) * lda); \
    } while (0)
#define LOAD_B(s, t) do { \
        uint32_t sb_ = sbase + (uint32_t)(s) * STG; \
        if (TRB == 0) { \
            const __half* pb_ = gB + (size_t)(t) * BKH; \
            _Pragma("unroll") \
            for (int i_ = 0; i_ < 8; i_++) \
                cp_async16(sb_ + dB + i_ * 2048u, pb_ + (size_t)(16 * i_) * ldb); \
        } else { \
            const __half* pb_ = gB + (size_t)(t) * BKH * ldb; \
            _Pragma("unroll") \
            for (int i_ = 0; i_ < 8; i_++) \
                cp_async16(sb_ + dB + i_ * 2048u, pb_ + (size_t)(8 * i_) * ldb); \
        } \
    } while (0)

    #pragma unroll
    for (int p = 0; p < 2; p++) {
        if (p < T) { LOAD_A(p, p); LOAD_B(p, p); }
        cp_commit();
    }

    // Prologue side-work (hidden under cp.async stage fill):
    // mode 4: 1/rowsum for this CTA's 128 rows.
    // mode 0: preload this tile's 128 bias values to smem.
    if (mode == 4) {
        const float* p = g_ps + ((size_t)(bz * SEQ + tile_m + tid)) * 32;
        float s = 0.f;
        #pragma unroll
        for (int i = 0; i < 8; i++) {
            float4 v = ((const float4*)p)[i];
            s += (v.x + v.y) + (v.z + v.w);
        }
        saux[tid] = 1.0f / s;
    } else if (mode == 0) {
        saux[tid] = aux[tile_n + tid];
    }

    // --- compute plan ---
    const int wm = wid & 1;
    const int wn = wid >> 1;
    const int lr = lane & 15;
    const int lcb = (lane >> 4) * 16;

    uint32_t aoff0[4], boff0[4];
    #pragma unroll
    for (int mi = 0; mi < 4; mi++)
        aoff0[mi] = swz((uint32_t)((wm * 64 + mi * 16 + lr) * 128 + lcb));
    if (TRB == 0) {
        #pragma unroll
        for (int nb = 0; nb < 4; nb++)
            boff0[nb] = 16384u + swz((uint32_t)((wn * 64 + nb * 16 + lr) * 128 + lcb));
    } else {
        #pragma unroll
        for (int nb = 0; nb < 4; nb++)
            boff0[nb] = 16384u + swzB((uint32_t)(lr * 256 + wn * 128 + nb * 32 + lcb));
    }

#define LDFRAG(af, bf, sa_, ks_) do { \
        _Pragma("unroll") \
        for (int mi_ = 0; mi_ < 4; mi_++) \
            ldsm_x4((af)[mi_], (sa_) + (aoff0[mi_] ^ (uint32_t)((ks_) * 32))); \
        if (TRB == 0) { \
            _Pragma("unroll") \
            for (int nb_ = 0; nb_ < 4; nb_++) \
                ldsm_x4((bf)[nb_], (sa_) + (boff0[nb_] ^ (uint32_t)((ks_) * 32))); \
        } else { \
            _Pragma("unroll") \
            for (int nb_ = 0; nb_ < 4; nb_++) \
                ldsm_x4_t((bf)[nb_], (sa_) + boff0[nb_] + (uint32_t)((ks_) * 4096)); \
        } \
    } while (0)

#define MMABLK(af, bf) do { \
        _Pragma("unroll") \
        for (int mi_ = 0; mi_ < 4; mi_++) \
            _Pragma("unroll") \
            for (int ni_ = 0; ni_ < 8; ni_++) { \
                uint32_t b0_ = (TRB == 0) ? (bf)[ni_ >> 1][ni_ & 1] \
                                          : (bf)[ni_ >> 1][(ni_ & 1) * 2]; \
                uint32_t b1_ = (TRB == 0) ? (bf)[ni_ >> 1][(ni_ & 1) + 2] \
                                          : (bf)[ni_ >> 1][(ni_ & 1) * 2 + 1]; \
                mma16816(acc[mi_][ni_], (af)[mi_], b0_, b1_); \
            } \
    } while (0)

    float acc[4][8][4] = {};
    uint32_t a0[4][4], b0[4][4], a1[4][4], b1[4][4];

    cp_wait1();
    __syncthreads();
    LDFRAG(a0, b0, sbase, 0);

    for (int t = 0; t < T; t++) {
        const uint32_t sa = sbase + (uint32_t)(t % NSTAGE) * STG;
        const bool pf = (t + 2 < T);
        const int ps = (t + 2) % NSTAGE;

        LDFRAG(a1, b1, sa, 1);
        MMABLK(a0, b0);                // ks 0
        if (pf) LOAD_A(ps, t + 2);     // issue global loads early, mid-compute
        LDFRAG(a0, b0, sa, 2);
        MMABLK(a1, b1);                // ks 1
        if (pf) LOAD_B(ps, t + 2);
        LDFRAG(a1, b1, sa, 3);
        MMABLK(a0, b0);                // ks 2

        cp_commit();
        MMABLK(a1, b1);                // ks 3 BEFORE wait: drain tensor work,
                                       // give the async group time to retire
        cp_wait1();
        __syncthreads();

        if (t + 1 < T)
            LDFRAG(a0, b0, sbase + (uint32_t)((t + 1) % NSTAGE) * STG, 0);
    }

    // --- epilogue ---
    const int er = lane >> 2;
    const int ec = (lane & 3) * 2;

    if (mode == 1 || mode == 4) {
        float* C = (float*)Cout + (size_t)bz * zC;
        #pragma unroll
        for (int mi = 0; mi < 4; mi++) {
            int mrow = wm * 64 + mi * 16 + er;
            int m0 = tile_m + mrow;
            float s0 = alpha, s1 = alpha;
            if (mode == 4) { s0 = saux[mrow]; s1 = saux[mrow + 8]; }
            #pragma unroll
            for (int ni = 0; ni < 8; ni++) {
                int n0 = tile_n + wn * 64 + ni * 8 + ec;
                float* c = acc[mi][ni];
                *(float2*)(C + (size_t)m0 * ldc + n0) =
                    make_float2(c[0] * s0, c[1] * s0);
                *(float2*)(C + (size_t)(m0 + 8) * ldc + n0) =
                    make_float2(c[2] * s1, c[3] * s1);
            }
        }
    } else {
        __half* C = (__half*)Cout + (size_t)bz * zC;
        float psum[4][2];
        #pragma unroll
        for (int mi = 0; mi < 4; mi++) { psum[mi][0] = 0.f; psum[mi][1] = 0.f; }

        const float l2e_alpha = alpha * 1.4426950408889634f;  // alpha * log2(e)

        #pragma unroll
        for (int mi = 0; mi < 4; mi++) {
            #pragma unroll
            for (int ni = 0; ni < 8; ni++) {
                int m0 = tile_m + wm * 64 + mi * 16 + er;
                int nl = wn * 64 + ni * 8 + ec;        // local n within tile
                int n0 = tile_n + nl;
                float* c = acc[mi][ni];
                __half2 h01, h23;
                if (mode == 3) {
                    h01 = h2_ex2(__floats2half2_rn(c[0] * l2e_alpha, c[1] * l2e_alpha));
                    h23 = h2_ex2(__floats2half2_rn(c[2] * l2e_alpha, c[3] * l2e_alpha));
                    float2 f01 = __half22float2(h01);
                    float2 f23 = __half22float2(h23);
                    psum[mi][0] += f01.x + f01.y;
                    psum[mi][1] += f23.x + f23.y;
                } else {
                    float bx = 0.f, by = 0.f;
                    if (mode == 0) { bx = saux[nl]; by = saux[nl + 1]; }
                    h01 = __floats2half2_rn(c[0] * alpha + bx, c[1] * alpha + by);
                    h23 = __floats2half2_rn(c[2] * alpha + bx, c[3] * alpha + by);
                }
                *(__half2*)(C + (size_t)m0 * ldc + n0) = h01;
                *(__half2*)(C + (size_t)(m0 + 8) * ldc + n0) = h23;
            }
        }

        if (mode == 3) {
            #pragma unroll
            for (int mi = 0; mi < 4; mi++) {
                #pragma unroll
                for (int h = 0; h < 2; h++) {
                    float v = psum[mi][h];
                    v += __shfl_xor_sync(0xffffffffu, v, 1);
                    v += __shfl_xor_sync(0xffffffffu, v, 2);
                    if ((lane & 3) == 0) {
                        int row = bz * SEQ + tile_m + wm * 64 + mi * 16 + er + h * 8;
                        g_ps[(size_t)row * 32 + blockIdx.x * 2 + wn] = v;
                    }
                }
            }
        }
    }
#undef LOAD_A
#undef LOAD_B
#undef LDFRAG
#undef MMABLK
}

// ---------------------------------------------------------------------------
// Combined prep: xh = fp16(x), Wc = fp16([W1;W2]), bc = [b1;b2]
// ---------------------------------------------------------------------------
__global__ __launch_bounds__(256)
void prep_all(const float* __restrict__ x,
              const float* __restrict__ W1, const float* __restrict__ W2,
              const float* __restrict__ b1, const float* __restrict__ b2,
              __half* __restrict__ xh, __half* __restrict__ Wc,
              float* __restrict__ bc)
{
    const long long nx4 = (long long)BATCH * SEQ * DIMD / 4;
    const long long nw4 = (long long)DIMD * DIMD / 4;
    long long i = (long long)blockIdx.x * blockDim.x + threadIdx.x;
    long long stride = (long long)gridDim.x * blockDim.x;

    for (long long j = i; j < nx4; j += stride) {
        float4 v = ((const float4*)x)[j];
        ((__half2*)xh)[2 * j + 0] = __floats2half2_rn(v.x, v.y);
        ((__half2*)xh)[2 * j + 1] = __floats2half2_rn(v.z, v.w);
    }
    for (long long j = i; j < 2 * nw4; j += stride) {
        const float* src = (j < nw4) ? W1 : W2;
        long long k = (j < nw4) ? j : j - nw4;
        float4 v = ((const float4*)src)[k];
        ((__half2*)Wc)[2 * j + 0] = __floats2half2_rn(v.x, v.y);
        ((__half2*)Wc)[2 * j + 1] = __floats2half2_rn(v.z, v.w);
    }
    for (long long j = i; j < 2 * DIMD; j += stride)
        bc[j] = (j < DIMD) ? b1[j] : b2[j - DIMD];
}

// ---------------------------------------------------------------------------
// Launch
// ---------------------------------------------------------------------------
extern "C" void kernel_launch(void* const* d_in, const int* in_sizes, int n_in,
                              void* d_out, int out_size)
{
    const float* x  = (const float*)d_in[0];
    const float* W1 = (const float*)d_in[1];
    const float* b1 = (const float*)d_in[2];
    const float* W2 = (const float*)d_in[3];
    const float* b2 = (const float*)d_in[4];
    float* out = (float*)d_out;

    __half *pxh, *pWc, *pVKh, *pSh;
    float *pbc;
    cudaGetSymbolAddress((void**)&pxh,  g_xh);
    cudaGetSymbolAddress((void**)&pWc,  g_Wc);
    cudaGetSymbolAddress((void**)&pbc,  g_bc);
    cudaGetSymbolAddress((void**)&pVKh, g_VKh);
    cudaGetSymbolAddress((void**)&pSh,  g_Sh);

    cudaFuncSetAttribute(mm_h16<0>, cudaFuncAttributeMaxDynamicSharedMemorySize, SMEM_SZ);
    cudaFuncSetAttribute(mm_h16<1>, cudaFuncAttributeMaxDynamicSharedMemorySize, SMEM_SZ);

    const float scale = 1.0f / 32.0f;  // 1/sqrt(1024)

    // 1. fp32 -> fp16 inputs/weights/biases (one kernel)
    prep_all<<<2048, 256>>>(x, W1, W2, b1, b2, pxh, pWc, pbc);

    // 2. [V | K] = fp16(x @ [W1;W2]^T + [b1;b2]) : M=16384, N=2048, K=1024 (NT)
    mm_h16<0><<<dim3(2 * DIMD / BN, BATCH * SEQ / BM, 1), 128, SMEM_SZ>>>(
        pxh, pWc, pbc, pVKh,
        DIMD, DIMD, 2 * DIMD, 0, 0, 0,
        DIMD, 1.0f, 0);

    // 3. P = fp16(exp(scale * K . V)) + partial row sums (NT, mode 3)
    mm_h16<0><<<dim3(SEQ / BN, SEQ / BM, BATCH), 128, SMEM_SZ>>>(
        pVKh + DIMD, pVKh, nullptr, pSh,
        2 * DIMD, 2 * DIMD, SEQ,
        (size_t)SEQ * 2 * DIMD, (size_t)SEQ * 2 * DIMD, (size_t)SEQ * SEQ,
        DIMD, scale, 3);

    // 4. out = inv[row] * (P @ V)  (NN via ldsm.trans, inv in-prologue, mode 4)
    mm_h16<1><<<dim3(DIMD / BN, SEQ / BM, BATCH), 128, SMEM_SZ>>>(
        pSh, pVKh, nullptr, out,
        SEQ, 2 * DIMD, DIMD,
        (size_t)SEQ * SEQ, (size_t)SEQ * 2 * DIMD, (size_t)SEQ * DIMD,
        SEQ, 1.0f, 4);
}